// round 16
// baseline (speedup 1.0000x reference)
#include <cuda_runtime.h>
#include <cuda_bf16.h>

// Lightcone-truncated quantum circuit sim — single warp, 8 qubits, GF(2)
// CNOT absorption + layer-0 product state + fused RY pairs.
//
// Reference: 25-qubit state, 8 layers of (RY all qubits, CNOT chain w=0..23),
// output <Z_q0>. Heisenberg lightcone (tight, validated in R13/R14): <Z_0>
// equals exactly the 8-qubit truncated circuit (RY q0..q7, CNOT w=0..6).
//
// State: 256 fp32 amps in one warp: index = (lane<<3)|reg; q0..q4 -> lane
// bits 4..0, q5..q7 -> reg bits 2..0.
//
// Lane-lane CNOTs (w=0..3) are absorbed into the GF(2) matrix L = G^k
// (tables SHM/SGN/CTR validated on hardware in R14, rel_err 1.1e-6).
//
// New this round:
//  * Layer 0 acts on |0>: result is a PRODUCT state, built directly with
//    ~15 multiplies — no shuffles, no butterflies.
//  * Layers 1..7: RY(w0,w1) and RY(w2,w3) each fused into ONE shuffle stage:
//    a' = u0*a + K1*p1 + K2*p2 + K3*p3,  p_i = shfl_xor(a, {m1, m2, m1^m2}),
//    K1 = +-c2*s1 (sign tau1), K2 = +-c1*s2 (sign tau2), K3 = +-s1*s2
//    (sign tau1*tau2 = parity(lane & (g1^g2)); the cross term eta =
//    parity(m2 & g1) is +1 for every layer/pair in these tables).
//    3 serial shuffle stages per layer instead of 5.

#define NQ    25
#define DEPTH 8

__global__ void __launch_bounds__(32, 1)
lightcone_qsim_fused_kernel(const float* __restrict__ theta, float* __restrict__ out)
{
    const unsigned FULL = 0xffffffffu;
    const int lane = threadIdx.x;

    // ---- parallel fast sincos precompute: 64 gates, 2 per lane ----
    __shared__ float csb[64], snb[64];
    #pragma unroll
    for (int t = 0; t < 2; ++t) {
        const int idx = lane + 32 * t;                 // idx = layer*8 + w
        const float ang = 0.5f * theta[(idx >> 3) * NQ + (idx & 7)];
        float s, c;
        __sincosf(ang, &s, &c);
        csb[idx] = c;
        snb[idx] = s;
    }
    __syncwarp();

    // SHM[k][w]: shfl_xor mask for RY on lane qubit w at layer k (col of G^{8-k})
    const int SHM[8][5] = {
        {0x10,0x08,0x04,0x02,0x01},
        {0x18,0x0C,0x06,0x03,0x01},
        {0x14,0x0A,0x05,0x02,0x01},
        {0x1E,0x0F,0x07,0x03,0x01},
        {0x11,0x08,0x04,0x02,0x01},
        {0x19,0x0C,0x06,0x03,0x01},
        {0x15,0x0A,0x05,0x02,0x01},
        {0x1F,0x0F,0x07,0x03,0x01},
    };
    // SGN[k][w]: sign row (row of G^k)
    const int SGN[8][5] = {
        {0x10,0x08,0x04,0x02,0x01},
        {0x10,0x18,0x1C,0x1E,0x1F},
        {0x10,0x08,0x14,0x0A,0x15},
        {0x10,0x18,0x0C,0x06,0x13},
        {0x10,0x08,0x04,0x02,0x11},
        {0x10,0x18,0x1C,0x1E,0x0F},
        {0x10,0x08,0x14,0x0A,0x05},
        {0x10,0x18,0x0C,0x06,0x03},
    };
    // CTR[k]: control row for the lane->reg CNOT (w=4) at layer k (row_0 of G^{k+1})
    const int CTR[8] = {0x1F,0x15,0x13,0x11,0x0F,0x05,0x03,0x01};

    float a[8];

    // ---- layer 0: product state (|0> -> prod of RY factors), then CNOT tail ----
    {
        float P = 1.0f;
        #pragma unroll
        for (int w = 0; w < 5; ++w)
            P *= ((lane >> (4 - w)) & 1) ? snb[w] : csb[w];
        #pragma unroll
        for (int r = 0; r < 8; ++r) {
            const float q = ((r & 4) ? snb[5] : csb[5])
                          * ((r & 2) ? snb[6] : csb[6])
                          * ((r & 1) ? snb[7] : csb[7]);
            a[r] = P * q;
        }
        // CNOT w=4 (ctrl = logical lane bit 0 after absorption)
        const bool ctrl = (__popc(lane & CTR[0]) & 1) != 0;
        #pragma unroll
        for (int r = 0; r < 4; ++r) {
            const float lo = a[r], hi4 = a[r | 4];
            a[r]     = ctrl ? hi4 : lo;
            a[r | 4] = ctrl ? lo  : hi4;
        }
        // CNOT w=5, w=6 (register renames)
        { float t = a[4]; a[4] = a[6]; a[6] = t;
          t = a[5]; a[5] = a[7]; a[7] = t; }
        { float t = a[2]; a[2] = a[3]; a[3] = t;
          t = a[6]; a[6] = a[7]; a[7] = t; }
    }

    // ---- layers 1..7 ----
    #pragma unroll
    for (int k = 1; k < DEPTH; ++k) {
        const float* tc = &csb[k * 8];
        const float* ts = &snb[k * 8];

        // fused RY pairs (w0,w1) and (w2,w3): one shuffle stage each
        #pragma unroll
        for (int pr = 0; pr < 2; ++pr) {
            const int wA = 2 * pr, wB = 2 * pr + 1;
            const float c1 = tc[wA], s1 = ts[wA];
            const float c2 = tc[wB], s2 = ts[wB];
            const int m1 = SHM[k][wA], m2 = SHM[k][wB], m3 = m1 ^ m2;
            const int g1 = SGN[k][wA], g2 = SGN[k][wB];
            const float u0 = c1 * c2, uA = c2 * s1, uB = c1 * s2, uC = s1 * s2;
            const bool b1  = (__popc(lane & g1) & 1) != 0;
            const bool b2  = (__popc(lane & g2) & 1) != 0;
            const bool b12 = b1 ^ b2;
            const float K1 = b1  ?  uA : -uA;
            const float K2 = b2  ?  uB : -uB;
            const float K3 = b12 ? -uC :  uC;   // tau1*tau2; eta = +1 (verified)
            #pragma unroll
            for (int r = 0; r < 8; ++r) {
                const float p1 = __shfl_xor_sync(FULL, a[r], m1);
                const float p2 = __shfl_xor_sync(FULL, a[r], m2);
                const float p3 = __shfl_xor_sync(FULL, a[r], m3);
                a[r] = fmaf(u0, a[r], fmaf(K1, p1, fmaf(K2, p2, K3 * p3)));
            }
        }
        // single RY w4
        {
            const float c = tc[4], s = ts[4];
            const int m = SHM[k][4];
            const bool hi = (__popc(lane & SGN[k][4]) & 1) != 0;
            const float ss = hi ? s : -s;
            #pragma unroll
            for (int r = 0; r < 8; ++r) {
                const float ca = c * a[r];                    // off critical path
                const float p = __shfl_xor_sync(FULL, a[r], m);
                a[r] = fmaf(ss, p, ca);
            }
        }
        // reg RYs q5..q7 (reg bits 2..0)
        #pragma unroll
        for (int w = 5; w < 8; ++w) {
            const float c = tc[w], s = ts[w];
            const int M = 1 << (7 - w);
            #pragma unroll
            for (int r = 0; r < 8; ++r) {
                if ((r & M) == 0) {
                    const float a0 = a[r], a1 = a[r | M];
                    a[r]     = fmaf(c, a0, -s * a1);
                    a[r | M] = fmaf(s, a0,  c * a1);
                }
            }
        }
        // CNOT tail: w=4 select, w=5/w=6 renames
        {
            const bool ctrl = (__popc(lane & CTR[k]) & 1) != 0;
            #pragma unroll
            for (int r = 0; r < 4; ++r) {
                const float lo = a[r], hi4 = a[r | 4];
                a[r]     = ctrl ? hi4 : lo;
                a[r | 4] = ctrl ? lo  : hi4;
            }
            { float t = a[4]; a[4] = a[6]; a[6] = t;
              t = a[5]; a[5] = a[7]; a[7] = t; }
            { float t = a[2]; a[2] = a[3]; a[3] = t;
              t = a[6]; a[6] = a[7]; a[7] = t; }
        }
    }

    // ---- <Z_0>: L = G^8 = I, sign = lane bit 4 ----
    float part = 0.0f;
    #pragma unroll
    for (int r = 0; r < 8; ++r) part = fmaf(a[r], a[r], part);
    part = (lane & 16) ? -part : part;

    #pragma unroll
    for (int off = 16; off > 0; off >>= 1)
        part += __shfl_xor_sync(FULL, part, off);

    if (lane == 0) out[0] = part;
}

extern "C" void kernel_launch(void* const* d_in, const int* in_sizes, int n_in,
                              void* d_out, int out_size)
{
    const float* theta = (const float*)d_in[0];   // [DEPTH, NQ] float32
    float* out = (float*)d_out;                   // scalar float32
    (void)in_sizes; (void)n_in; (void)out_size;
    lightcone_qsim_fused_kernel<<<1, 32>>>(theta, out);
}

// round 17
// speedup vs baseline: 1.0337x; 1.0337x over previous
#include <cuda_runtime.h>
#include <cuda_bf16.h>

// Lightcone-truncated quantum circuit sim — single warp, 8 qubits, GF(2)
// CNOT absorption, layer-0 product state, lane-RYs fused into TWO shuffle
// stages per layer (triple + pair).
//
// Reference: 25-qubit state, 8 layers of (RY all qubits, CNOT chain w=0..23),
// output <Z_q0>. Heisenberg lightcone (validated R13-R16): <Z_0> equals
// exactly the 8-qubit truncated circuit (RY q0..q7, CNOT w=0..6).
//
// State: 256 fp32 amps in one warp: index = (lane<<3)|reg; q0..q4 -> lane
// bits, q5..q7 -> reg bits. Lane-lane CNOTs (w=0..3) absorbed into L = G^k
// (SHM/SGN/CTR tables validated on HW, rel_err ~1e-6).
//
// Fusion of commuting RYs on lane qubits i,j: composing the butterflies
// introduces a cross sign eps_ij = (-1)^popc(m_j & g_i). For ALL pairs within
// {w0,w1,w2} and for (w3,w4), across every layer of the tables, m_j & g_i = 0
// => eps = +1, so the fused 8-term (triple) / 4-term (pair) updates use plain
// coefficient products with signs prod(sigma_i), sigma_i = parity(lane&g_i).

#define NQ    25
#define DEPTH 8

__global__ void __launch_bounds__(32, 1)
lightcone_qsim_fused2_kernel(const float* __restrict__ theta, float* __restrict__ out)
{
    const unsigned FULL = 0xffffffffu;
    const int lane = threadIdx.x;

    // ---- parallel fast sincos precompute: 64 gates, 2 per lane ----
    __shared__ float csb[64], snb[64];
    #pragma unroll
    for (int t = 0; t < 2; ++t) {
        const int idx = lane + 32 * t;                 // idx = layer*8 + w
        const float ang = 0.5f * theta[(idx >> 3) * NQ + (idx & 7)];
        float s, c;
        __sincosf(ang, &s, &c);
        csb[idx] = c;
        snb[idx] = s;
    }
    __syncwarp();

    // SHM[k][w]: shfl_xor mask for RY on lane qubit w at layer k (col of G^{8-k})
    const int SHM[8][5] = {
        {0x10,0x08,0x04,0x02,0x01},
        {0x18,0x0C,0x06,0x03,0x01},
        {0x14,0x0A,0x05,0x02,0x01},
        {0x1E,0x0F,0x07,0x03,0x01},
        {0x11,0x08,0x04,0x02,0x01},
        {0x19,0x0C,0x06,0x03,0x01},
        {0x15,0x0A,0x05,0x02,0x01},
        {0x1F,0x0F,0x07,0x03,0x01},
    };
    // SGN[k][w]: sign row (row of G^k)
    const int SGN[8][5] = {
        {0x10,0x08,0x04,0x02,0x01},
        {0x10,0x18,0x1C,0x1E,0x1F},
        {0x10,0x08,0x14,0x0A,0x15},
        {0x10,0x18,0x0C,0x06,0x13},
        {0x10,0x08,0x04,0x02,0x11},
        {0x10,0x18,0x1C,0x1E,0x0F},
        {0x10,0x08,0x14,0x0A,0x05},
        {0x10,0x18,0x0C,0x06,0x03},
    };
    // CTR[k]: control row for the lane->reg CNOT (w=4) at layer k (row_0 of G^{k+1})
    const int CTR[8] = {0x1F,0x15,0x13,0x11,0x0F,0x05,0x03,0x01};

    float a[8];

    // ---- layer 0: product state (|0> -> prod of RY factors), then CNOT tail ----
    {
        float P = 1.0f;
        #pragma unroll
        for (int w = 0; w < 5; ++w)
            P *= ((lane >> (4 - w)) & 1) ? snb[w] : csb[w];
        #pragma unroll
        for (int r = 0; r < 8; ++r) {
            const float q = ((r & 4) ? snb[5] : csb[5])
                          * ((r & 2) ? snb[6] : csb[6])
                          * ((r & 1) ? snb[7] : csb[7]);
            a[r] = P * q;
        }
        const bool ctrl = (__popc(lane & CTR[0]) & 1) != 0;
        #pragma unroll
        for (int r = 0; r < 4; ++r) {
            const float lo = a[r], hi4 = a[r | 4];
            a[r]     = ctrl ? hi4 : lo;
            a[r | 4] = ctrl ? lo  : hi4;
        }
        { float t = a[4]; a[4] = a[6]; a[6] = t;
          t = a[5]; a[5] = a[7]; a[7] = t; }
        { float t = a[2]; a[2] = a[3]; a[3] = t;
          t = a[6]; a[6] = a[7]; a[7] = t; }
    }

    // ---- layers 1..7 ----
    #pragma unroll
    for (int k = 1; k < DEPTH; ++k) {
        const float* tc = &csb[k * 8];
        const float* ts = &snb[k * 8];

        // ===== TRIPLE stage: fused RY(w0) RY(w1) RY(w2), one shuffle stage =====
        {
            const float c1 = tc[0], s1 = ts[0];
            const float c2 = tc[1], s2 = ts[1];
            const float c3 = tc[2], s3 = ts[2];
            const int m1 = SHM[k][0], m2 = SHM[k][1], m3 = SHM[k][2];
            const int m12 = m1 ^ m2, m13 = m1 ^ m3, m23 = m2 ^ m3, m123 = m12 ^ m3;
            const bool b1 = (__popc(lane & SGN[k][0]) & 1) != 0;
            const bool b2 = (__popc(lane & SGN[k][1]) & 1) != 0;
            const bool b3 = (__popc(lane & SGN[k][2]) & 1) != 0;

            const float cc23 = c2 * c3, sc23 = s2 * c3, cs23 = c2 * s3, ss23 = s2 * s3;
            const float u0   = c1 * cc23;
            const float uA   = s1 * cc23, uB  = c1 * sc23, uC  = c1 * cs23;
            const float uAB  = s1 * sc23, uAC = s1 * cs23, uBC = c1 * ss23;
            const float uABC = s1 * ss23;

            const float K1   =  b1            ?  uA   : -uA;
            const float K2   =  b2            ?  uB   : -uB;
            const float K3   =  b3            ?  uC   : -uC;
            const float K12  = (b1 ^ b2)      ? -uAB  :  uAB;
            const float K13  = (b1 ^ b3)      ? -uAC  :  uAC;
            const float K23  = (b2 ^ b3)      ? -uBC  :  uBC;
            const float K123 = (b1 ^ b2 ^ b3) ?  uABC : -uABC;

            #pragma unroll
            for (int r = 0; r < 8; ++r) {
                const float p1   = __shfl_xor_sync(FULL, a[r], m1);
                const float p2   = __shfl_xor_sync(FULL, a[r], m2);
                const float p3   = __shfl_xor_sync(FULL, a[r], m3);
                const float p12  = __shfl_xor_sync(FULL, a[r], m12);
                const float p13  = __shfl_xor_sync(FULL, a[r], m13);
                const float p23  = __shfl_xor_sync(FULL, a[r], m23);
                const float p123 = __shfl_xor_sync(FULL, a[r], m123);
                const float q0 = fmaf(u0,  a[r], K1   * p1);
                const float q1 = fmaf(K2,  p2,   K3   * p3);
                const float q2 = fmaf(K12, p12,  K13  * p13);
                const float q3 = fmaf(K23, p23,  K123 * p123);
                a[r] = (q0 + q1) + (q2 + q3);
            }
        }
        // ===== PAIR stage: fused RY(w3) RY(w4) =====
        {
            const float c1 = tc[3], s1 = ts[3];
            const float c2 = tc[4], s2 = ts[4];
            const int m1 = SHM[k][3], m2 = SHM[k][4], m3 = m1 ^ m2;
            const bool b1 = (__popc(lane & SGN[k][3]) & 1) != 0;
            const bool b2 = (__popc(lane & SGN[k][4]) & 1) != 0;
            const float u0 = c1 * c2, uA = c2 * s1, uB = c1 * s2, uC = s1 * s2;
            const float K1 =  b1       ?  uA : -uA;
            const float K2 =  b2       ?  uB : -uB;
            const float K3 = (b1 ^ b2) ? -uC :  uC;
            #pragma unroll
            for (int r = 0; r < 8; ++r) {
                const float p1 = __shfl_xor_sync(FULL, a[r], m1);
                const float p2 = __shfl_xor_sync(FULL, a[r], m2);
                const float p3 = __shfl_xor_sync(FULL, a[r], m3);
                a[r] = fmaf(u0, a[r], K1 * p1) + fmaf(K2, p2, K3 * p3);
            }
        }
        // ===== reg RYs q5..q7 (reg bits 2..0) =====
        #pragma unroll
        for (int w = 5; w < 8; ++w) {
            const float c = tc[w], s = ts[w];
            const int M = 1 << (7 - w);
            #pragma unroll
            for (int r = 0; r < 8; ++r) {
                if ((r & M) == 0) {
                    const float a0 = a[r], a1 = a[r | M];
                    a[r]     = fmaf(c, a0, -s * a1);
                    a[r | M] = fmaf(s, a0,  c * a1);
                }
            }
        }
        // ===== CNOT tail: w=4 select, w=5/w=6 register renames =====
        {
            const bool ctrl = (__popc(lane & CTR[k]) & 1) != 0;
            #pragma unroll
            for (int r = 0; r < 4; ++r) {
                const float lo = a[r], hi4 = a[r | 4];
                a[r]     = ctrl ? hi4 : lo;
                a[r | 4] = ctrl ? lo  : hi4;
            }
            { float t = a[4]; a[4] = a[6]; a[6] = t;
              t = a[5]; a[5] = a[7]; a[7] = t; }
            { float t = a[2]; a[2] = a[3]; a[3] = t;
              t = a[6]; a[6] = a[7]; a[7] = t; }
        }
    }

    // ---- <Z_0>: L = G^8 = I, sign = lane bit 4; balanced square-sum tree ----
    const float q0 = fmaf(a[0], a[0], a[1] * a[1]);
    const float q1 = fmaf(a[2], a[2], a[3] * a[3]);
    const float q2 = fmaf(a[4], a[4], a[5] * a[5]);
    const float q3 = fmaf(a[6], a[6], a[7] * a[7]);
    float part = (q0 + q1) + (q2 + q3);
    part = (lane & 16) ? -part : part;

    #pragma unroll
    for (int off = 16; off > 0; off >>= 1)
        part += __shfl_xor_sync(FULL, part, off);

    if (lane == 0) out[0] = part;
}

extern "C" void kernel_launch(void* const* d_in, const int* in_sizes, int n_in,
                              void* d_out, int out_size)
{
    const float* theta = (const float*)d_in[0];   // [DEPTH, NQ] float32
    float* out = (float*)d_out;                   // scalar float32
    (void)in_sizes; (void)n_in; (void)out_size;
    lightcone_qsim_fused2_kernel<<<1, 32>>>(theta, out);
}